// round 2
// baseline (speedup 1.0000x reference)
#include <cuda_runtime.h>
#include <math.h>

#define G   640
#define NXK 320
#define MK  65536
#define NCK 8
#define NTK 8
#define NIMG 64          // t*NCK + c
#define LB  4            // FFT lines per block
#define FT  256          // FFT kernel threads

// ---- scratch (device globals; no runtime allocation) ----
__device__ float2 d_grids[(size_t)NIMG * G * G];        // ~210 MB
__device__ float2 d_buf1 [(size_t)NIMG * G * NXK];      // ~105 MB  [img][row][cy]
__device__ float2 d_buf2 [(size_t)NIMG * NXK * NXK];    // ~52 MB   [img][cx][cy]
__device__ float2 d_fimg [(size_t)NTK * NXK * NXK];     // ~6.6 MB

__constant__ float2 W5c[5] = {
    { 1.0f,                   0.0f },
    { 0.30901699437494745f,   0.9510565162951535f },
    {-0.8090169943749473f,    0.5877852522924731f },
    {-0.8090169943749475f,   -0.587785252292473f  },
    { 0.30901699437494723f,  -0.9510565162951536f }
};

// ---------------- zero grids ----------------
__global__ void zero_kernel() {
    size_t i = (size_t)blockIdx.x * blockDim.x + threadIdx.x;
    float4* p = reinterpret_cast<float4*>(d_grids);
    size_t n4 = (size_t)NIMG * G * G / 2;   // float2 pairs -> float4
    if (i < n4) p[i] = make_float4(0.f, 0.f, 0.f, 0.f);
}

// ---------------- gridding (scatter) ----------------
__global__ void grid_kernel(const float* __restrict__ kr, const float* __restrict__ ki,
                            const float* __restrict__ traj, const float* __restrict__ dcf) {
    int m = blockIdx.x * blockDim.x + threadIdx.x;
    int t = blockIdx.y;
    if (m >= MK) return;
    float tx = traj[m * 16 + t];
    float ty = traj[m * 16 + 8 + t];
    float w  = dcf[m * 8 + t];

    float u = (tx + 0.5f) * (float)G;
    float v = (ty + 0.5f) * (float)G;
    float u0 = floorf(u), v0 = floorf(v);
    float du = u - u0, dv = v - v0;
    int i0 = ((int)u0) % G; if (i0 < 0) i0 += G;
    int j0 = ((int)v0) % G; if (j0 < 0) j0 += G;
    int i1 = (i0 + 1 == G) ? 0 : i0 + 1;
    int j1 = (j0 + 1 == G) ? 0 : j0 + 1;

    float w00 = (1.f - du) * (1.f - dv) * w;
    float w10 = du * (1.f - dv) * w;
    float w01 = (1.f - du) * dv * w;
    float w11 = du * dv * w;
    int b00 = i0 * G + j0, b10 = i1 * G + j0, b01 = i0 * G + j1, b11 = i1 * G + j1;

#pragma unroll
    for (int c = 0; c < NCK; c++) {
        float re = kr[c * MK + m];
        float im = ki[c * MK + m];
        float2* g = d_grids + (size_t)(t * NCK + c) * G * G;
        atomicAdd(&g[b00].x, re * w00); atomicAdd(&g[b00].y, im * w00);
        atomicAdd(&g[b10].x, re * w10); atomicAdd(&g[b10].y, im * w10);
        atomicAdd(&g[b01].x, re * w01); atomicAdd(&g[b01].y, im * w01);
        atomicAdd(&g[b11].x, re * w11); atomicAdd(&g[b11].y, im * w11);
    }
}

// ---------------- batched 640-point inverse FFT (unnormalized, + sign) ----------------
// 640 = 5 * 128 : radix-5 + twiddle, then 5 x 128-pt radix-2 Stockham (self-sorting).
// pass==1 : FFT rows of d_grids, keep 320 cropped columns -> d_buf1[img][row][cy]
// pass==2 : FFT columns of d_buf1, keep 320 cropped rows  -> d_buf2[img][cx][cy]
__global__ void fft_pass_kernel(int pass) {
    __shared__ float2 SA[LB * G];
    __shared__ float2 SB[LB * G];
    int tid = threadIdx.x;

    int img, line0;
    if (pass == 1) {
        img   = blockIdx.x / (G / LB);
        line0 = (blockIdx.x % (G / LB)) * LB;   // row0
        const float2* in = d_grids + (size_t)img * G * G + (size_t)line0 * G;
        for (int i = tid; i < LB * G; i += FT) {
            int e = i % G, l = i / G;
            SA[l * G + e] = in[(size_t)l * G + e];
        }
    } else {
        img   = blockIdx.x / (NXK / LB);
        line0 = (blockIdx.x % (NXK / LB)) * LB; // cy0
        const float2* in = d_buf1 + (size_t)img * G * NXK + line0;
        for (int i = tid; i < LB * G; i += FT) {
            int l = i % LB, e = i / LB;
            SA[l * G + e] = in[(size_t)e * NXK + l];
        }
    }
    __syncthreads();

    // Step A: 128 radix-5 DFTs per line + twiddle  -> SB[l][k1*128 + n2]
    for (int i = tid; i < LB * 128; i += FT) {
        int l = i >> 7, n2 = i & 127;
        float2 x0 = SA[l * G + n2];
        float2 x1 = SA[l * G + n2 + 128];
        float2 x2 = SA[l * G + n2 + 256];
        float2 x3 = SA[l * G + n2 + 384];
        float2 x4 = SA[l * G + n2 + 512];
#pragma unroll
        for (int k1 = 0; k1 < 5; k1++) {
            float2 acc = x0;
            int r = 0;
            float2 xs[4] = {x1, x2, x3, x4};
#pragma unroll
            for (int n1 = 1; n1 < 5; n1++) {
                r += k1; if (r >= 5) r -= 5;
                float2 wv = W5c[r];
                acc.x += xs[n1 - 1].x * wv.x - xs[n1 - 1].y * wv.y;
                acc.y += xs[n1 - 1].x * wv.y + xs[n1 - 1].y * wv.x;
            }
            // twiddle e^{+2pi i * n2*k1/640}
            float ang = (float)(n2 * k1) * 9.817477042468103e-3f;
            float sn, cs; __sincosf(ang, &sn, &cs);
            SB[l * G + k1 * 128 + n2] = make_float2(acc.x * cs - acc.y * sn,
                                                    acc.x * sn + acc.y * cs);
        }
    }
    __syncthreads();

    // Step B: five independent 128-pt Stockham FFTs per line (7 radix-2 stages)
    float2* src = SB;
    float2* dst = SA;
    int n = 128, s = 1;
#pragma unroll
    for (int st = 0; st < 7; st++) {
        int mh = n >> 1;
        float th = 6.283185307179586f / (float)n;
        for (int i = tid; i < LB * 5 * 64; i += FT) {
            int l = i / 320, r = i - l * 320;
            int f = r >> 6, b = r & 63;
            int p = b / s, q = b - p * s;
            int cb = l * G + f * 128;
            float2 a = src[cb + q + s * p];
            float2 c = src[cb + q + s * (p + mh)];
            float sn, cs; __sincosf(th * (float)p, &sn, &cs);
            float2 dd = make_float2(a.x - c.x, a.y - c.y);
            dst[cb + q + s * 2 * p]       = make_float2(a.x + c.x, a.y + c.y);
            dst[cb + q + s * (2 * p + 1)] = make_float2(dd.x * cs - dd.y * sn,
                                                        dd.x * sn + dd.y * cs);
        }
        __syncthreads();
        float2* tp = src; src = dst; dst = tp;
        n >>= 1; s <<= 1;
    }
    // result in src : X[5*k2 + k1] = src[l*G + k1*128 + k2]

    if (pass == 1) {
        float2* out = d_buf1 + (size_t)img * G * NXK + (size_t)line0 * NXK;
        for (int i = tid; i < LB * NXK; i += FT) {
            int cy = i % NXK, l = i / NXK;
            int k = (cy < 160) ? cy + 480 : cy - 160;   // k = (cy+480) % 640
            out[(size_t)l * NXK + cy] = src[l * G + (k % 5) * 128 + k / 5];
        }
    } else {
        float2* out = d_buf2 + (size_t)img * NXK * NXK + line0;
        for (int i = tid; i < LB * NXK; i += FT) {
            int l = i % LB, cx = i / LB;
            int k = (cx < 160) ? cx + 480 : cx - 160;
            out[(size_t)cx * NXK + l] = src[l * G + (k % 5) * 128 + k / 5];
        }
    }
}

// ---------------- coil combine + sign + deapodization + 1/G^2 ----------------
__global__ void combine_kernel(const float* __restrict__ csr, const float* __restrict__ csi) {
    int pix = blockIdx.x * blockDim.x + threadIdx.x;
    int t = blockIdx.y;
    if (pix >= NXK * NXK) return;
    int cx = pix / NXK, cy = pix % NXK;

    float2 acc = make_float2(0.f, 0.f);
#pragma unroll
    for (int c = 0; c < NCK; c++) {
        float2 v = d_buf2[(size_t)(t * NCK + c) * NXK * NXK + pix];
        float cr = csr[c * NXK * NXK + pix];
        float ci = csi[c * NXK * NXK + pix];
        acc.x += cr * v.x + ci * v.y;   // conj(csm) * v
        acc.y += cr * v.y - ci * v.x;
    }
    float xv = (float)(cx - 160) * (1.0f / 640.0f);
    float yv = (float)(cy - 160) * (1.0f / 640.0f);
    float sx = (cx == 160) ? 1.0f : sinpif(xv) / (3.14159265358979f * xv);
    float sy = (cy == 160) ? 1.0f : sinpif(yv) / (3.14159265358979f * yv);
    float sgn = ((cx + cy) & 1) ? -1.0f : 1.0f;
    float scale = sgn / (409600.0f * (sx * sx) * (sy * sy));
    d_fimg[(size_t)t * NXK * NXK + pix] = make_float2(acc.x * scale, acc.y * scale);
}

// ---------------- motion warp + frame sum ----------------
__global__ void warp_kernel(const float* __restrict__ motions, float* __restrict__ out) {
    int pix = blockIdx.x * blockDim.x + threadIdx.x;
    if (pix >= NXK * NXK) return;
    int x = pix / NXK, y = pix % NXK;

    float2 acc = make_float2(0.f, 0.f);
#pragma unroll
    for (int t = 0; t < NTK; t++) {
        float f0 = motions[(pix * 2 + 0) * NTK + t];
        float f1 = motions[(pix * 2 + 1) * NTK + t];
        float xs = fminf(fmaxf((float)x + f0, 0.f), 319.f);
        float ys = fminf(fmaxf((float)y + f1, 0.f), 319.f);
        float x0f = floorf(xs), y0f = floorf(ys);
        int x0 = (int)x0f, y0 = (int)y0f;
        int x1 = min(x0 + 1, 319), y1 = min(y0 + 1, 319);
        float dx = xs - x0f, dy = ys - y0f;
        const float2* im = d_fimg + (size_t)t * NXK * NXK;
        float2 v00 = im[x0 * NXK + y0];
        float2 v10 = im[x1 * NXK + y0];
        float2 v01 = im[x0 * NXK + y1];
        float2 v11 = im[x1 * NXK + y1];
        float w00 = (1.f - dx) * (1.f - dy), w10 = dx * (1.f - dy);
        float w01 = (1.f - dx) * dy,         w11 = dx * dy;
        acc.x += w00 * v00.x + w10 * v10.x + w01 * v01.x + w11 * v11.x;
        acc.y += w00 * v00.y + w10 * v10.y + w01 * v01.y + w11 * v11.y;
    }
    out[pix * 2 + 0] = acc.x;
    out[pix * 2 + 1] = acc.y;
}

// ---------------- launch ----------------
extern "C" void kernel_launch(void* const* d_in, const int* in_sizes, int n_in,
                              void* d_out, int out_size) {
    const float* kspace_r = (const float*)d_in[0];
    const float* kspace_i = (const float*)d_in[1];
    const float* traj     = (const float*)d_in[2];
    const float* csm_r    = (const float*)d_in[3];
    const float* csm_i    = (const float*)d_in[4];
    const float* dcf      = (const float*)d_in[5];
    const float* motions  = (const float*)d_in[6];
    float* out = (float*)d_out;

    // 1) zero grids
    {
        size_t n4 = (size_t)NIMG * G * G / 2;
        int thr = 512;
        int blk = (int)((n4 + thr - 1) / thr);
        zero_kernel<<<blk, thr>>>();
    }
    // 2) gridding scatter
    {
        dim3 grid(MK / 256, NTK);
        grid_kernel<<<grid, 256>>>(kspace_r, kspace_i, traj, dcf);
    }
    // 3) FFT pass 1 (rows)
    fft_pass_kernel<<<NIMG * (G / LB), FT>>>(1);
    // 4) FFT pass 2 (columns, cropped)
    fft_pass_kernel<<<NIMG * (NXK / LB), FT>>>(2);
    // 5) coil combine + deapodize
    {
        dim3 grid((NXK * NXK + 255) / 256, NTK);
        combine_kernel<<<grid, 256>>>(csm_r, csm_i);
    }
    // 6) warp + frame sum
    warp_kernel<<<(NXK * NXK + 255) / 256, 256>>>(motions, out);
}

// round 7
// speedup vs baseline: 1.1640x; 1.1640x over previous
#include <cuda_runtime.h>
#include <math.h>

#define G   640
#define NXK 320
#define MK  65536
#define NCK 8
#define NTK 8
#define NIMG 64          // t*NCK + c
#define LB  4            // FFT lines per block
#define FT  256          // FFT kernel threads

// ---- scratch (device globals; no runtime allocation) ----
__device__ float2 d_grids[(size_t)NIMG * G * G];        // ~210 MB
__device__ float2 d_buf1 [(size_t)NIMG * G * NXK];      // ~105 MB  [img][row][cy]
__device__ float2 d_fimg [(size_t)NTK * NXK * NXK];     // ~6.6 MB

__constant__ float2 W5c[5] = {
    { 1.0f,                   0.0f },
    { 0.30901699437494745f,   0.9510565162951535f },
    {-0.8090169943749473f,    0.5877852522924731f },
    {-0.8090169943749475f,   -0.587785252292473f  },
    { 0.30901699437494723f,  -0.9510565162951536f }
};

// ---------------- zero grids ----------------
__global__ void zero_kernel() {
    size_t i = (size_t)blockIdx.x * blockDim.x + threadIdx.x;
    float4* p = reinterpret_cast<float4*>(d_grids);
    size_t n4 = (size_t)NIMG * G * G / 2;
    if (i < n4) p[i] = make_float4(0.f, 0.f, 0.f, 0.f);
}

// ---------------- gridding (scatter, vector red.add.v2.f32) ----------------
__device__ __forceinline__ void redv2(float2* p, float re, float im) {
    asm volatile("red.global.add.v2.f32 [%0], {%1, %2};"
                 :: "l"(p), "f"(re), "f"(im) : "memory");
}

__global__ void grid_kernel(const float* __restrict__ kr, const float* __restrict__ ki,
                            const float* __restrict__ traj, const float* __restrict__ dcf) {
    int m = blockIdx.x * blockDim.x + threadIdx.x;
    int t = blockIdx.y;
    if (m >= MK) return;
    float tx = traj[m * 16 + t];
    float ty = traj[m * 16 + 8 + t];
    float w  = dcf[m * 8 + t];

    float u = (tx + 0.5f) * (float)G;
    float v = (ty + 0.5f) * (float)G;
    float u0 = floorf(u), v0 = floorf(v);
    float du = u - u0, dv = v - v0;
    int i0 = ((int)u0) % G; if (i0 < 0) i0 += G;
    int j0 = ((int)v0) % G; if (j0 < 0) j0 += G;
    int i1 = (i0 + 1 == G) ? 0 : i0 + 1;
    int j1 = (j0 + 1 == G) ? 0 : j0 + 1;

    float w00 = (1.f - du) * (1.f - dv) * w;
    float w10 = du * (1.f - dv) * w;
    float w01 = (1.f - du) * dv * w;
    float w11 = du * dv * w;
    int b00 = i0 * G + j0, b10 = i1 * G + j0, b01 = i0 * G + j1, b11 = i1 * G + j1;

#pragma unroll
    for (int c = 0; c < NCK; c++) {
        float re = kr[c * MK + m];
        float im = ki[c * MK + m];
        float2* g = d_grids + (size_t)(t * NCK + c) * G * G;
        redv2(&g[b00], re * w00, im * w00);
        redv2(&g[b10], re * w10, im * w10);
        redv2(&g[b01], re * w01, im * w01);
        redv2(&g[b11], re * w11, im * w11);
    }
}

// ======== shared FFT building blocks (640 = 5 * 128; sign = +i, unnormalized) =========

// Step A: 128 radix-5 DFTs per line + twiddle.  SA -> SB, layout SB[l][k1*128 + n2]
__device__ __forceinline__ void step_radix5(const float2* SA, float2* SB, int tid) {
    for (int i = tid; i < LB * 128; i += FT) {
        int l = i >> 7, n2 = i & 127;
        float2 x0 = SA[l * G + n2];
        float2 x1 = SA[l * G + n2 + 128];
        float2 x2 = SA[l * G + n2 + 256];
        float2 x3 = SA[l * G + n2 + 384];
        float2 x4 = SA[l * G + n2 + 512];
#pragma unroll
        for (int k1 = 0; k1 < 5; k1++) {
            float2 acc = x0;
            int r = 0;
            float2 xs[4] = {x1, x2, x3, x4};
#pragma unroll
            for (int n1 = 1; n1 < 5; n1++) {
                r += k1; if (r >= 5) r -= 5;
                float2 wv = W5c[r];
                acc.x += xs[n1 - 1].x * wv.x - xs[n1 - 1].y * wv.y;
                acc.y += xs[n1 - 1].x * wv.y + xs[n1 - 1].y * wv.x;
            }
            float ang = (float)(n2 * k1) * 9.817477042468103e-3f; // 2*pi/640
            float sn, cs; __sincosf(ang, &sn, &cs);
            SB[l * G + k1 * 128 + n2] = make_float2(acc.x * cs - acc.y * sn,
                                                    acc.x * sn + acc.y * cs);
        }
    }
}

// radix-4 Stockham stage: (N_, S_) -> (N_/4, 4*S_).  MH = N_/4, (N_/4)*S_ == 32.
template<int N_, int S_>
__device__ __forceinline__ void stage_radix4(const float2* src, float2* dst, int tid) {
    const int MH = N_ / 4;
    for (int i = tid; i < LB * 160; i += FT) {
        int l = i / 160, r = i - l * 160;
        int f = r >> 5, b = r & 31;
        int p = b / S_, q = b - p * S_;
        int cb = l * G + f * 128;
        float2 x0 = src[cb + q + S_ * p];
        float2 x1 = src[cb + q + S_ * (p + MH)];
        float2 x2 = src[cb + q + S_ * (p + 2 * MH)];
        float2 x3 = src[cb + q + S_ * (p + 3 * MH)];
        // +i-sign radix-4 butterfly
        float2 t0 = make_float2(x0.x + x2.x, x0.y + x2.y);
        float2 t1 = make_float2(x0.x - x2.x, x0.y - x2.y);
        float2 t2 = make_float2(x1.x + x3.x, x1.y + x3.y);
        float2 t3 = make_float2(-(x1.y - x3.y), x1.x - x3.x); // +i*(x1-x3)
        float2 y0 = make_float2(t0.x + t2.x, t0.y + t2.y);
        float2 y1 = make_float2(t1.x + t3.x, t1.y + t3.y);
        float2 y2 = make_float2(t0.x - t2.x, t0.y - t2.y);
        float2 y3 = make_float2(t1.x - t3.x, t1.y - t3.y);
        float ang = 6.283185307179586f / (float)N_ * (float)p;
        float s1, c1; __sincosf(ang, &s1, &c1);
        float c2 = c1 * c1 - s1 * s1, s2 = 2.f * c1 * s1;      // w^2
        float c3 = c2 * c1 - s2 * s1, s3 = c2 * s1 + s2 * c1;  // w^3
        int ob = cb + q;
        dst[ob + S_ * (4 * p + 0)] = y0;
        dst[ob + S_ * (4 * p + 1)] = make_float2(y1.x * c1 - y1.y * s1, y1.x * s1 + y1.y * c1);
        dst[ob + S_ * (4 * p + 2)] = make_float2(y2.x * c2 - y2.y * s2, y2.x * s2 + y2.y * c2);
        dst[ob + S_ * (4 * p + 3)] = make_float2(y3.x * c3 - y3.y * s3, y3.x * s3 + y3.y * c3);
    }
}

// final radix-2 stage: n=2, s=64 (twiddle = 1)
__device__ __forceinline__ void stage_radix2_final(const float2* src, float2* dst, int tid) {
    for (int i = tid; i < LB * 320; i += FT) {
        int l = i / 320, r = i - l * 320;
        int f = r >> 6, q = r & 63;
        int cb = l * G + f * 128;
        float2 a = src[cb + q];
        float2 b = src[cb + q + 64];
        dst[cb + q]      = make_float2(a.x + b.x, a.y + b.y);
        dst[cb + q + 64] = make_float2(a.x - b.x, a.y - b.y);
    }
}

// run full 128-pt FFT pipeline: SA(input lines) -> result in SB
__device__ __forceinline__ void fft640(float2* SA, float2* SB, int tid) {
    step_radix5(SA, SB, tid);          __syncthreads();
    stage_radix4<128, 1>(SB, SA, tid); __syncthreads();
    stage_radix4<32, 4>(SA, SB, tid);  __syncthreads();
    stage_radix4<8, 16>(SB, SA, tid);  __syncthreads();
    stage_radix2_final(SA, SB, tid);   __syncthreads();
    // X[5*k2+k1] = SB[l*G + k1*128 + k2]
}

// ---------------- pass 1: FFT rows of d_grids, keep cropped 320 columns ----------------
__global__ void fft_rows_kernel() {
    __shared__ float2 SA[LB * G];
    __shared__ float2 SB[LB * G];
    int tid = threadIdx.x;
    int img   = blockIdx.x / (G / LB);
    int line0 = (blockIdx.x % (G / LB)) * LB;

    const float2* in = d_grids + (size_t)img * G * G + (size_t)line0 * G;
    for (int i = tid; i < LB * G; i += FT) {
        int e = i % G, l = i / G;
        SA[l * G + e] = in[(size_t)l * G + e];
    }
    __syncthreads();
    fft640(SA, SB, tid);

    float2* out = d_buf1 + (size_t)img * G * NXK + (size_t)line0 * NXK;
    for (int i = tid; i < LB * NXK; i += FT) {
        int cy = i % NXK, l = i / NXK;
        int k = (cy < 160) ? cy + 480 : cy - 160;   // k = (cy+480) % 640
        out[(size_t)l * NXK + cy] = SB[l * G + (k % 5) * 128 + k / 5];
    }
}

// ---------------- pass 2 fused: column FFT over all coils + conj-CSM combine + deapod ----------------
__global__ void fft_cols_combine_kernel(const float* __restrict__ csr,
                                        const float* __restrict__ csi) {
    __shared__ float2 SA[LB * G];
    __shared__ float2 SB[LB * G];
    int tid = threadIdx.x;
    int t   = blockIdx.x / (NXK / LB);
    int cy0 = (blockIdx.x % (NXK / LB)) * LB;

    // per-thread output assignment: idx = tid + j*FT -> cx = idx/4, l = idx%4
    float accR[5], accI[5];
    int soff[5], coff[5];
#pragma unroll
    for (int j = 0; j < 5; j++) {
        accR[j] = 0.f; accI[j] = 0.f;
        int idx = tid + j * FT;
        int cx = idx >> 2, l = idx & 3;
        int k = (cx < 160) ? cx + 480 : cx - 160;
        soff[j] = l * G + (k % 5) * 128 + k / 5;
        coff[j] = cx * NXK + cy0 + l;
    }

    for (int c = 0; c < NCK; c++) {
        int img = t * NCK + c;
        const float2* in = d_buf1 + (size_t)img * G * NXK + cy0;
        for (int i = tid; i < LB * G; i += FT) {
            int l = i % LB, e = i / LB;
            SA[l * G + e] = in[(size_t)e * NXK + l];
        }
        __syncthreads();
        fft640(SA, SB, tid);
#pragma unroll
        for (int j = 0; j < 5; j++) {
            float2 v = SB[soff[j]];
            float cr = csr[c * NXK * NXK + coff[j]];
            float ci = csi[c * NXK * NXK + coff[j]];
            accR[j] += cr * v.x + ci * v.y;   // conj(csm) * v
            accI[j] += cr * v.y - ci * v.x;
        }
        __syncthreads();   // protect SB before next coil's stages overwrite
    }

    float2* out = d_fimg + (size_t)t * NXK * NXK;
#pragma unroll
    for (int j = 0; j < 5; j++) {
        int idx = tid + j * FT;
        int cx = idx >> 2, cy = cy0 + (idx & 3);
        float xv = (float)(cx - 160) * (1.0f / 640.0f);
        float yv = (float)(cy - 160) * (1.0f / 640.0f);
        float sx = (cx == 160) ? 1.0f : sinpif(xv) / (3.14159265358979f * xv);
        float sy = (cy == 160) ? 1.0f : sinpif(yv) / (3.14159265358979f * yv);
        float sgn = ((cx + cy) & 1) ? -1.0f : 1.0f;
        float scale = sgn / (409600.0f * (sx * sx) * (sy * sy));
        out[coff[j]] = make_float2(accR[j] * scale, accI[j] * scale);
    }
}

// ---------------- motion warp + frame sum ----------------
__global__ void warp_kernel(const float* __restrict__ motions, float* __restrict__ out) {
    int pix = blockIdx.x * blockDim.x + threadIdx.x;
    if (pix >= NXK * NXK) return;
    int x = pix / NXK, y = pix % NXK;

    float2 acc = make_float2(0.f, 0.f);
#pragma unroll
    for (int t = 0; t < NTK; t++) {
        float f0 = motions[(pix * 2 + 0) * NTK + t];
        float f1 = motions[(pix * 2 + 1) * NTK + t];
        float xs = fminf(fmaxf((float)x + f0, 0.f), 319.f);
        float ys = fminf(fmaxf((float)y + f1, 0.f), 319.f);
        float x0f = floorf(xs), y0f = floorf(ys);
        int x0 = (int)x0f, y0 = (int)y0f;
        int x1 = min(x0 + 1, 319), y1 = min(y0 + 1, 319);
        float dx = xs - x0f, dy = ys - y0f;
        const float2* im = d_fimg + (size_t)t * NXK * NXK;
        float2 v00 = im[x0 * NXK + y0];
        float2 v10 = im[x1 * NXK + y0];
        float2 v01 = im[x0 * NXK + y1];
        float2 v11 = im[x1 * NXK + y1];
        float w00 = (1.f - dx) * (1.f - dy), w10 = dx * (1.f - dy);
        float w01 = (1.f - dx) * dy,         w11 = dx * dy;
        acc.x += w00 * v00.x + w10 * v10.x + w01 * v01.x + w11 * v11.x;
        acc.y += w00 * v00.y + w10 * v10.y + w01 * v01.y + w11 * v11.y;
    }
    out[pix * 2 + 0] = acc.x;
    out[pix * 2 + 1] = acc.y;
}

// ---------------- launch ----------------
extern "C" void kernel_launch(void* const* d_in, const int* in_sizes, int n_in,
                              void* d_out, int out_size) {
    const float* kspace_r = (const float*)d_in[0];
    const float* kspace_i = (const float*)d_in[1];
    const float* traj     = (const float*)d_in[2];
    const float* csm_r    = (const float*)d_in[3];
    const float* csm_i    = (const float*)d_in[4];
    const float* dcf      = (const float*)d_in[5];
    const float* motions  = (const float*)d_in[6];
    float* out = (float*)d_out;

    {
        size_t n4 = (size_t)NIMG * G * G / 2;
        int thr = 512;
        int blk = (int)((n4 + thr - 1) / thr);
        zero_kernel<<<blk, thr>>>();
    }
    {
        dim3 grid(MK / 256, NTK);
        grid_kernel<<<grid, 256>>>(kspace_r, kspace_i, traj, dcf);
    }
    fft_rows_kernel<<<NIMG * (G / LB), FT>>>();
    fft_cols_combine_kernel<<<NTK * (NXK / LB), FT>>>(csm_r, csm_i);
    warp_kernel<<<(NXK * NXK + 255) / 256, 256>>>(motions, out);
}

// round 8
// speedup vs baseline: 1.4306x; 1.2291x over previous
#include <cuda_runtime.h>
#include <math.h>

#define G   640
#define NXK 320
#define MK  65536
#define NCK 8
#define NTK 8
#define LB  4            // FFT lines per block (one coil-quad)
#define FT  256          // FFT kernel threads
#define LS  642          // padded smem line stride (float2) to avoid bank conflicts

// ---- scratch (device globals; no runtime allocation) ----
// d_grids: [t][cq][i][j][c4]  (coil quads innermost -> 32B-contiguous scatter targets)
__device__ float2 d_grids[(size_t)NTK * 2 * G * G * 4];        // ~210 MB
// d_buf1:  [t][cq][row][cy][c4]
__device__ float2 d_buf1 [(size_t)NTK * 2 * G * NXK * 4];      // ~105 MB
// d_buf2:  [t][cx][cy][c8]
__device__ float2 d_buf2 [(size_t)NTK * NXK * NXK * NCK];      // ~52 MB
__device__ float2 d_fimg [(size_t)NTK * NXK * NXK];            // ~6.6 MB

__constant__ float2 W5c[5] = {
    { 1.0f,                   0.0f },
    { 0.30901699437494745f,   0.9510565162951535f },
    {-0.8090169943749473f,    0.5877852522924731f },
    {-0.8090169943749475f,   -0.587785252292473f  },
    { 0.30901699437494723f,  -0.9510565162951536f }
};

// ---------------- zero grids ----------------
__global__ void zero_kernel() {
    size_t i = (size_t)blockIdx.x * blockDim.x + threadIdx.x;
    float4* p = reinterpret_cast<float4*>(d_grids);
    size_t n4 = (size_t)NTK * 2 * G * G * 4 / 2;
    if (i < n4) p[i] = make_float4(0.f, 0.f, 0.f, 0.f);
}

// ---------------- gridding (scatter, red.add.v4.f32 to contiguous coil quads) ----------------
__device__ __forceinline__ void redv4(float2* p, float2 a, float2 b) {
    asm volatile("red.global.add.v4.f32 [%0], {%1, %2, %3, %4};"
                 :: "l"(p), "f"(a.x), "f"(a.y), "f"(b.x), "f"(b.y) : "memory");
}

__global__ void grid_kernel(const float* __restrict__ kr, const float* __restrict__ ki,
                            const float* __restrict__ traj, const float* __restrict__ dcf) {
    int m = blockIdx.x * blockDim.x + threadIdx.x;
    int t = blockIdx.y;
    if (m >= MK) return;
    float tx = traj[m * 16 + t];
    float ty = traj[m * 16 + 8 + t];
    float w  = dcf[m * 8 + t];

    float u = (tx + 0.5f) * (float)G;
    float v = (ty + 0.5f) * (float)G;
    float u0 = floorf(u), v0 = floorf(v);
    float du = u - u0, dv = v - v0;
    int i0 = ((int)u0) % G; if (i0 < 0) i0 += G;
    int j0 = ((int)v0) % G; if (j0 < 0) j0 += G;
    int i1 = (i0 + 1 == G) ? 0 : i0 + 1;
    int j1 = (j0 + 1 == G) ? 0 : j0 + 1;

    float w00 = (1.f - du) * (1.f - dv) * w;
    float w10 = du * (1.f - dv) * w;
    float w01 = (1.f - du) * dv * w;
    float w11 = du * dv * w;

#pragma unroll
    for (int cq = 0; cq < 2; cq++) {
        // load 4 coils of this quad
        float2 d[4];
#pragma unroll
        for (int c4 = 0; c4 < 4; c4++) {
            int c = cq * 4 + c4;
            d[c4] = make_float2(kr[c * MK + m], ki[c * MK + m]);
        }
        float2* base = d_grids + ((size_t)(t * 2 + cq) * G * G) * 4;
        float2* p00 = base + (size_t)(i0 * G + j0) * 4;
        float2* p10 = base + (size_t)(i1 * G + j0) * 4;
        float2* p01 = base + (size_t)(i0 * G + j1) * 4;
        float2* p11 = base + (size_t)(i1 * G + j1) * 4;
#define CORNER(P, W) \
        redv4(P,     make_float2(d[0].x*(W), d[0].y*(W)), make_float2(d[1].x*(W), d[1].y*(W))); \
        redv4(P + 2, make_float2(d[2].x*(W), d[2].y*(W)), make_float2(d[3].x*(W), d[3].y*(W)));
        CORNER(p00, w00)
        CORNER(p10, w10)
        CORNER(p01, w01)
        CORNER(p11, w11)
#undef CORNER
    }
}

// ======== shared FFT building blocks (640 = 5 * 128; sign = +i, unnormalized) =========
// lines live at SA[l*LS + e], e in [0,640)

__device__ __forceinline__ void step_radix5(const float2* SA, float2* SB, int tid) {
    for (int i = tid; i < LB * 128; i += FT) {
        int l = i >> 7, n2 = i & 127;
        float2 x0 = SA[l * LS + n2];
        float2 x1 = SA[l * LS + n2 + 128];
        float2 x2 = SA[l * LS + n2 + 256];
        float2 x3 = SA[l * LS + n2 + 384];
        float2 x4 = SA[l * LS + n2 + 512];
#pragma unroll
        for (int k1 = 0; k1 < 5; k1++) {
            float2 acc = x0;
            int r = 0;
            float2 xs[4] = {x1, x2, x3, x4};
#pragma unroll
            for (int n1 = 1; n1 < 5; n1++) {
                r += k1; if (r >= 5) r -= 5;
                float2 wv = W5c[r];
                acc.x += xs[n1 - 1].x * wv.x - xs[n1 - 1].y * wv.y;
                acc.y += xs[n1 - 1].x * wv.y + xs[n1 - 1].y * wv.x;
            }
            float ang = (float)(n2 * k1) * 9.817477042468103e-3f; // 2*pi/640
            float sn, cs; __sincosf(ang, &sn, &cs);
            SB[l * LS + k1 * 128 + n2] = make_float2(acc.x * cs - acc.y * sn,
                                                     acc.x * sn + acc.y * cs);
        }
    }
}

template<int N_, int S_>
__device__ __forceinline__ void stage_radix4(const float2* src, float2* dst, int tid) {
    const int MH = N_ / 4;
    for (int i = tid; i < LB * 160; i += FT) {
        int l = i / 160, r = i - l * 160;
        int f = r >> 5, b = r & 31;
        int p = b / S_, q = b - p * S_;
        int cb = l * LS + f * 128;
        float2 x0 = src[cb + q + S_ * p];
        float2 x1 = src[cb + q + S_ * (p + MH)];
        float2 x2 = src[cb + q + S_ * (p + 2 * MH)];
        float2 x3 = src[cb + q + S_ * (p + 3 * MH)];
        float2 t0 = make_float2(x0.x + x2.x, x0.y + x2.y);
        float2 t1 = make_float2(x0.x - x2.x, x0.y - x2.y);
        float2 t2 = make_float2(x1.x + x3.x, x1.y + x3.y);
        float2 t3 = make_float2(-(x1.y - x3.y), x1.x - x3.x); // +i*(x1-x3)
        float2 y0 = make_float2(t0.x + t2.x, t0.y + t2.y);
        float2 y1 = make_float2(t1.x + t3.x, t1.y + t3.y);
        float2 y2 = make_float2(t0.x - t2.x, t0.y - t2.y);
        float2 y3 = make_float2(t1.x - t3.x, t1.y - t3.y);
        float ang = 6.283185307179586f / (float)N_ * (float)p;
        float s1, c1; __sincosf(ang, &s1, &c1);
        float c2 = c1 * c1 - s1 * s1, s2 = 2.f * c1 * s1;
        float c3 = c2 * c1 - s2 * s1, s3 = c2 * s1 + s2 * c1;
        int ob = cb + q;
        dst[ob + S_ * (4 * p + 0)] = y0;
        dst[ob + S_ * (4 * p + 1)] = make_float2(y1.x * c1 - y1.y * s1, y1.x * s1 + y1.y * c1);
        dst[ob + S_ * (4 * p + 2)] = make_float2(y2.x * c2 - y2.y * s2, y2.x * s2 + y2.y * c2);
        dst[ob + S_ * (4 * p + 3)] = make_float2(y3.x * c3 - y3.y * s3, y3.x * s3 + y3.y * c3);
    }
}

__device__ __forceinline__ void stage_radix2_final(const float2* src, float2* dst, int tid) {
    for (int i = tid; i < LB * 320; i += FT) {
        int l = i / 320, r = i - l * 320;
        int f = r >> 6, q = r & 63;
        int cb = l * LS + f * 128;
        float2 a = src[cb + q];
        float2 b = src[cb + q + 64];
        dst[cb + q]      = make_float2(a.x + b.x, a.y + b.y);
        dst[cb + q + 64] = make_float2(a.x - b.x, a.y - b.y);
    }
}

__device__ __forceinline__ void fft640(float2* SA, float2* SB, int tid) {
    step_radix5(SA, SB, tid);          __syncthreads();
    stage_radix4<128, 1>(SB, SA, tid); __syncthreads();
    stage_radix4<32, 4>(SA, SB, tid);  __syncthreads();
    stage_radix4<8, 16>(SB, SA, tid);  __syncthreads();
    stage_radix2_final(SA, SB, tid);   __syncthreads();
    // X[5*k2+k1] = SB[l*LS + k1*128 + k2]
}

// ---------------- pass 1: FFT rows, keep cropped 320 columns ----------------
// block = (tq, row). loads the 4 interleaved coil lines of one row (fully coalesced)
__global__ void fft_rows_kernel() {
    __shared__ float2 SA[LB * LS];
    __shared__ float2 SB[LB * LS];
    int tid = threadIdx.x;
    int tq  = blockIdx.x / G;      // t*2 + cq
    int row = blockIdx.x % G;

    const float2* in = d_grids + ((size_t)tq * G + row) * G * 4;
    for (int v = tid; v < G * 4; v += FT) {
        int c = v & 3, j = v >> 2;
        SA[c * LS + j] = in[v];
    }
    __syncthreads();
    fft640(SA, SB, tid);

    float2* out = d_buf1 + ((size_t)tq * G + row) * NXK * 4;
    for (int v = tid; v < NXK * 4; v += FT) {
        int c = v & 3, cy = v >> 2;
        int k = (cy < 160) ? cy + 480 : cy - 160;   // (cy+480) % 640
        out[v] = SB[c * LS + (k % 5) * 128 + k / 5];
    }
}

// ---------------- pass 2: FFT columns, keep cropped 320 rows ----------------
// block = (tq, cy). reads 32B sectors down the column, writes coil-interleaved d_buf2
__global__ void fft_cols_kernel() {
    __shared__ float2 SA[LB * LS];
    __shared__ float2 SB[LB * LS];
    int tid = threadIdx.x;
    int tq = blockIdx.x / NXK;
    int cy = blockIdx.x % NXK;

    const float2* in = d_buf1 + (size_t)tq * G * NXK * 4 + (size_t)cy * 4;
    for (int v = tid; v < G * 4; v += FT) {
        int c = v & 3, i = v >> 2;
        SA[c * LS + i] = in[(size_t)i * NXK * 4 + c];
    }
    __syncthreads();
    fft640(SA, SB, tid);

    int t = tq >> 1, cq = tq & 1;
    float2* out = d_buf2 + (size_t)t * NXK * NXK * NCK + cq * 4;
    for (int v = tid; v < NXK * 4; v += FT) {
        int c = v & 3, cx = v >> 2;
        int k = (cx < 160) ? cx + 480 : cx - 160;
        out[((size_t)cx * NXK + cy) * NCK + c] = SB[c * LS + (k % 5) * 128 + k / 5];
    }
}

// ---------------- coil combine + sign + deapodization + 1/G^2 ----------------
__global__ void combine_kernel(const float* __restrict__ csr, const float* __restrict__ csi) {
    int pix = blockIdx.x * blockDim.x + threadIdx.x;
    int t = blockIdx.y;
    if (pix >= NXK * NXK) return;
    int cx = pix / NXK, cy = pix % NXK;

    const float4* p = reinterpret_cast<const float4*>(d_buf2 + ((size_t)t * NXK * NXK + pix) * NCK);
    float2 acc = make_float2(0.f, 0.f);
#pragma unroll
    for (int h = 0; h < 4; h++) {            // 2 coils per float4
        float4 vv = p[h];
        int c0 = h * 2, c1 = h * 2 + 1;
        float cr0 = csr[c0 * NXK * NXK + pix], ci0 = csi[c0 * NXK * NXK + pix];
        float cr1 = csr[c1 * NXK * NXK + pix], ci1 = csi[c1 * NXK * NXK + pix];
        acc.x += cr0 * vv.x + ci0 * vv.y + cr1 * vv.z + ci1 * vv.w;
        acc.y += cr0 * vv.y - ci0 * vv.x + cr1 * vv.w - ci1 * vv.z;
    }
    float xv = (float)(cx - 160) * (1.0f / 640.0f);
    float yv = (float)(cy - 160) * (1.0f / 640.0f);
    float sx = (cx == 160) ? 1.0f : sinpif(xv) / (3.14159265358979f * xv);
    float sy = (cy == 160) ? 1.0f : sinpif(yv) / (3.14159265358979f * yv);
    float sgn = ((cx + cy) & 1) ? -1.0f : 1.0f;
    float scale = sgn / (409600.0f * (sx * sx) * (sy * sy));
    d_fimg[(size_t)t * NXK * NXK + pix] = make_float2(acc.x * scale, acc.y * scale);
}

// ---------------- motion warp + frame sum ----------------
__global__ void warp_kernel(const float* __restrict__ motions, float* __restrict__ out) {
    int pix = blockIdx.x * blockDim.x + threadIdx.x;
    if (pix >= NXK * NXK) return;
    int x = pix / NXK, y = pix % NXK;

    float2 acc = make_float2(0.f, 0.f);
#pragma unroll
    for (int t = 0; t < NTK; t++) {
        float f0 = motions[(pix * 2 + 0) * NTK + t];
        float f1 = motions[(pix * 2 + 1) * NTK + t];
        float xs = fminf(fmaxf((float)x + f0, 0.f), 319.f);
        float ys = fminf(fmaxf((float)y + f1, 0.f), 319.f);
        float x0f = floorf(xs), y0f = floorf(ys);
        int x0 = (int)x0f, y0 = (int)y0f;
        int x1 = min(x0 + 1, 319), y1 = min(y0 + 1, 319);
        float dx = xs - x0f, dy = ys - y0f;
        const float2* im = d_fimg + (size_t)t * NXK * NXK;
        float2 v00 = im[x0 * NXK + y0];
        float2 v10 = im[x1 * NXK + y0];
        float2 v01 = im[x0 * NXK + y1];
        float2 v11 = im[x1 * NXK + y1];
        float w00 = (1.f - dx) * (1.f - dy), w10 = dx * (1.f - dy);
        float w01 = (1.f - dx) * dy,         w11 = dx * dy;
        acc.x += w00 * v00.x + w10 * v10.x + w01 * v01.x + w11 * v11.x;
        acc.y += w00 * v00.y + w10 * v10.y + w01 * v01.y + w11 * v11.y;
    }
    out[pix * 2 + 0] = acc.x;
    out[pix * 2 + 1] = acc.y;
}

// ---------------- launch ----------------
extern "C" void kernel_launch(void* const* d_in, const int* in_sizes, int n_in,
                              void* d_out, int out_size) {
    const float* kspace_r = (const float*)d_in[0];
    const float* kspace_i = (const float*)d_in[1];
    const float* traj     = (const float*)d_in[2];
    const float* csm_r    = (const float*)d_in[3];
    const float* csm_i    = (const float*)d_in[4];
    const float* dcf      = (const float*)d_in[5];
    const float* motions  = (const float*)d_in[6];
    float* out = (float*)d_out;

    {
        size_t n4 = (size_t)NTK * 2 * G * G * 4 / 2;
        int thr = 512;
        int blk = (int)((n4 + thr - 1) / thr);
        zero_kernel<<<blk, thr>>>();
    }
    {
        dim3 grid(MK / 256, NTK);
        grid_kernel<<<grid, 256>>>(kspace_r, kspace_i, traj, dcf);
    }
    fft_rows_kernel<<<NTK * 2 * G, FT>>>();
    fft_cols_kernel<<<NTK * 2 * NXK, FT>>>();
    {
        dim3 grid((NXK * NXK + 255) / 256, NTK);
        combine_kernel<<<grid, 256>>>(csm_r, csm_i);
    }
    warp_kernel<<<(NXK * NXK + 255) / 256, 256>>>(motions, out);
}